// round 1
// baseline (speedup 1.0000x reference)
#include <cuda_runtime.h>

// AdapLoss: per-sample MSE/L1/Huber means over (8, 160^3) fp32, branch, scalar mean.
// Pure HBM-streaming reduction. Deterministic two-stage tree reduce (no atomics).

#define DELTA 5.0f

constexpr int BS = 8;
constexpr long long NPER = 4096000LL;      // 160^3 elements per sample
constexpr int V4 = 1024000;                // NPER / 4 float4's per sample
constexpr int BLOCKS_X = 128;              // blocks per sample
constexpr int THREADS = 512;

// Stage-1 partial sums: [sample][block][{sum_e2, sum_abs, sum_huber}]
__device__ float g_partials[BS][BLOCKS_X][3];

__global__ __launch_bounds__(THREADS)
void adaploss_partial(const float* __restrict__ pred, const float* __restrict__ tru) {
    const int s = blockIdx.y;
    const float4* __restrict__ p4 = reinterpret_cast<const float4*>(pred + (long long)s * NPER);
    const float4* __restrict__ t4 = reinterpret_cast<const float4*>(tru  + (long long)s * NPER);

    float s2 = 0.0f, s1 = 0.0f, sh = 0.0f;

    for (int i = blockIdx.x * THREADS + threadIdx.x; i < V4; i += BLOCKS_X * THREADS) {
        float4 a = p4[i];
        float4 b = t4[i];
        float e0 = a.x - b.x, e1 = a.y - b.y, e2 = a.z - b.z, e3 = a.w - b.w;
        float a0 = fabsf(e0), a1 = fabsf(e1), a2 = fabsf(e2), a3 = fabsf(e3);

        s2 += e0 * e0 + e1 * e1 + e2 * e2 + e3 * e3;
        s1 += a0 + a1 + a2 + a3;

        float h0 = (a0 <= DELTA) ? 0.5f * e0 * e0 : DELTA * (a0 - 0.5f * DELTA);
        float h1 = (a1 <= DELTA) ? 0.5f * e1 * e1 : DELTA * (a1 - 0.5f * DELTA);
        float h2 = (a2 <= DELTA) ? 0.5f * e2 * e2 : DELTA * (a2 - 0.5f * DELTA);
        float h3 = (a3 <= DELTA) ? 0.5f * e3 * e3 : DELTA * (a3 - 0.5f * DELTA);
        sh += h0 + h1 + h2 + h3;
    }

    // warp reduce (3 values)
    #pragma unroll
    for (int off = 16; off > 0; off >>= 1) {
        s2 += __shfl_down_sync(0xFFFFFFFFu, s2, off);
        s1 += __shfl_down_sync(0xFFFFFFFFu, s1, off);
        sh += __shfl_down_sync(0xFFFFFFFFu, sh, off);
    }

    __shared__ float sm2[THREADS / 32], sm1[THREADS / 32], smh[THREADS / 32];
    const int lane = threadIdx.x & 31;
    const int wid  = threadIdx.x >> 5;
    if (lane == 0) { sm2[wid] = s2; sm1[wid] = s1; smh[wid] = sh; }
    __syncthreads();

    if (wid == 0) {
        const int NW = THREADS / 32;
        float v2 = (lane < NW) ? sm2[lane] : 0.0f;
        float v1 = (lane < NW) ? sm1[lane] : 0.0f;
        float vh = (lane < NW) ? smh[lane] : 0.0f;
        #pragma unroll
        for (int off = 8; off > 0; off >>= 1) {
            v2 += __shfl_down_sync(0xFFFFFFFFu, v2, off);
            v1 += __shfl_down_sync(0xFFFFFFFFu, v1, off);
            vh += __shfl_down_sync(0xFFFFFFFFu, vh, off);
        }
        if (lane == 0) {
            g_partials[s][blockIdx.x][0] = v2;
            g_partials[s][blockIdx.x][1] = v1;
            g_partials[s][blockIdx.x][2] = vh;
        }
    }
}

// Stage 2: one block of 128 threads reduces 128 partials per sample, applies
// the branch, averages over samples, writes the scalar.
__global__ __launch_bounds__(BLOCKS_X)
void adaploss_final(float* __restrict__ out) {
    __shared__ double sh2[BLOCKS_X], sh1[BLOCKS_X], shh[BLOCKS_X];
    __shared__ double acc;
    const int t = threadIdx.x;
    if (t == 0) acc = 0.0;

    for (int s = 0; s < BS; s++) {
        sh2[t] = (double)g_partials[s][t][0];
        sh1[t] = (double)g_partials[s][t][1];
        shh[t] = (double)g_partials[s][t][2];
        __syncthreads();
        for (int off = BLOCKS_X / 2; off > 0; off >>= 1) {
            if (t < off) {
                sh2[t] += sh2[t + off];
                sh1[t] += sh1[t + off];
                shh[t] += shh[t + off];
            }
            __syncthreads();
        }
        if (t == 0) {
            double inv = 1.0 / (double)NPER;
            double L2 = sh2[0] * inv;
            double L1 = sh1[0] * inv;
            double HU = shh[0] * inv;
            bool use_l2 = (L2 <= 1.0) || (L2 < L1 * L1);
            acc += use_l2 ? L2 : HU;
        }
        __syncthreads();
    }
    if (t == 0) out[0] = (float)(acc / (double)BS);
}

extern "C" void kernel_launch(void* const* d_in, const int* in_sizes, int n_in,
                              void* d_out, int out_size) {
    const float* pred = (const float*)d_in[0];
    const float* tru  = (const float*)d_in[1];
    float* out = (float*)d_out;

    dim3 grid(BLOCKS_X, BS);
    adaploss_partial<<<grid, THREADS>>>(pred, tru);
    adaploss_final<<<1, BLOCKS_X>>>(out);
}

// round 4
// speedup vs baseline: 1.2428x; 1.2428x over previous
#include <cuda_runtime.h>

// AdapLoss fused single-kernel: per-sample MSE/L1/Huber means over (8, 160^3) fp32,
// branch select, scalar mean. HBM-streaming reduction with last-block-done finish.

#define DELTA 5.0f

constexpr int BS = 8;
constexpr long long NPER = 4096000LL;      // 160^3 elements per sample
constexpr int V4 = 1024000;                // NPER / 4 float4's per sample
constexpr int BLOCKS_X = 74;               // 8 * 74 = 592 = 148 SMs * 4 CTAs -> one wave
constexpr int THREADS = 512;
constexpr int TOTAL_BLOCKS = BS * BLOCKS_X;

// Stage-1 partial sums: [sample][block][{sum_e2, sum_abs, sum_huber}]
__device__ float g_partials[BS][BLOCKS_X][3];
__device__ unsigned int g_counter;   // zero-init at module load; last block resets to 0

__global__ __launch_bounds__(THREADS)
void adaploss_fused(const float* __restrict__ pred, const float* __restrict__ tru,
                    float* __restrict__ out) {
    const int s = blockIdx.y;
    const float4* __restrict__ p4 = reinterpret_cast<const float4*>(pred + (long long)s * NPER);
    const float4* __restrict__ t4 = reinterpret_cast<const float4*>(tru  + (long long)s * NPER);

    float s2 = 0.0f, s1 = 0.0f, sh = 0.0f;

    for (int i = blockIdx.x * THREADS + threadIdx.x; i < V4; i += BLOCKS_X * THREADS) {
        float4 a = p4[i];
        float4 b = t4[i];
        float e0 = a.x - b.x, e1 = a.y - b.y, e2 = a.z - b.z, e3 = a.w - b.w;
        float a0 = fabsf(e0), a1 = fabsf(e1), a2 = fabsf(e2), a3 = fabsf(e3);

        s2 += e0 * e0 + e1 * e1 + e2 * e2 + e3 * e3;
        s1 += a0 + a1 + a2 + a3;

        float h0 = (a0 <= DELTA) ? 0.5f * e0 * e0 : DELTA * (a0 - 0.5f * DELTA);
        float h1 = (a1 <= DELTA) ? 0.5f * e1 * e1 : DELTA * (a1 - 0.5f * DELTA);
        float h2 = (a2 <= DELTA) ? 0.5f * e2 * e2 : DELTA * (a2 - 0.5f * DELTA);
        float h3 = (a3 <= DELTA) ? 0.5f * e3 * e3 : DELTA * (a3 - 0.5f * DELTA);
        sh += h0 + h1 + h2 + h3;
    }

    // intra-warp reduce
    #pragma unroll
    for (int off = 16; off > 0; off >>= 1) {
        s2 += __shfl_down_sync(0xFFFFFFFFu, s2, off);
        s1 += __shfl_down_sync(0xFFFFFFFFu, s1, off);
        sh += __shfl_down_sync(0xFFFFFFFFu, sh, off);
    }

    __shared__ float sm2[THREADS / 32], sm1[THREADS / 32], smh[THREADS / 32];
    __shared__ bool is_last;
    const int lane = threadIdx.x & 31;
    const int wid  = threadIdx.x >> 5;
    if (lane == 0) { sm2[wid] = s2; sm1[wid] = s1; smh[wid] = sh; }
    __syncthreads();

    if (wid == 0) {
        const int NW = THREADS / 32;
        float v2 = (lane < NW) ? sm2[lane] : 0.0f;
        float v1 = (lane < NW) ? sm1[lane] : 0.0f;
        float vh = (lane < NW) ? smh[lane] : 0.0f;
        #pragma unroll
        for (int off = 8; off > 0; off >>= 1) {
            v2 += __shfl_down_sync(0xFFFFFFFFu, v2, off);
            v1 += __shfl_down_sync(0xFFFFFFFFu, v1, off);
            vh += __shfl_down_sync(0xFFFFFFFFu, vh, off);
        }
        if (lane == 0) {
            g_partials[s][blockIdx.x][0] = v2;
            g_partials[s][blockIdx.x][1] = v1;
            g_partials[s][blockIdx.x][2] = vh;
            __threadfence();
            unsigned int prev = atomicAdd(&g_counter, 1u);
            is_last = (prev == (unsigned int)(TOTAL_BLOCKS - 1));
        }
    }
    __syncthreads();
    if (!is_last) return;

    // ---- last block: final reduction over all partials ----
    // 512 threads: 64 threads per sample; thread (ss, j) sums partial j (+ j+64 if valid).
    const int t  = threadIdx.x;
    const int ss = t >> 6;       // 0..7
    const int j  = t & 63;       // 0..63

    double d2 = (j < BLOCKS_X) ? (double)g_partials[ss][j][0] : 0.0;
    double d1 = (j < BLOCKS_X) ? (double)g_partials[ss][j][1] : 0.0;
    double dh = (j < BLOCKS_X) ? (double)g_partials[ss][j][2] : 0.0;
    if (j + 64 < BLOCKS_X) {
        d2 += (double)g_partials[ss][j + 64][0];
        d1 += (double)g_partials[ss][j + 64][1];
        dh += (double)g_partials[ss][j + 64][2];
    }

    // each warp is fully within one sample (64-thread groups, 32-aligned)
    #pragma unroll
    for (int off = 16; off > 0; off >>= 1) {
        d2 += __shfl_down_sync(0xFFFFFFFFu, d2, off);
        d1 += __shfl_down_sync(0xFFFFFFFFu, d1, off);
        dh += __shfl_down_sync(0xFFFFFFFFu, dh, off);
    }

    __shared__ double w2[16], w1[16], wh[16];
    __shared__ double per_sample[BS];
    if ((t & 31) == 0) { w2[t >> 5] = d2; w1[t >> 5] = d1; wh[t >> 5] = dh; }
    __syncthreads();

    if (t < BS) {
        // sample t lives in warp slots 2t and 2t+1
        double inv = 1.0 / (double)NPER;
        double L2 = (w2[2 * t] + w2[2 * t + 1]) * inv;
        double L1 = (w1[2 * t] + w1[2 * t + 1]) * inv;
        double HU = (wh[2 * t] + wh[2 * t + 1]) * inv;
        bool use_l2 = (L2 <= 1.0) || (L2 < L1 * L1);
        per_sample[t] = use_l2 ? L2 : HU;
    }
    __syncthreads();

    if (t == 0) {
        double acc = 0.0;
        #pragma unroll
        for (int k = 0; k < BS; k++) acc += per_sample[k];
        out[0] = (float)(acc / (double)BS);
        g_counter = 0u;   // reset for next graph replay
    }
}

extern "C" void kernel_launch(void* const* d_in, const int* in_sizes, int n_in,
                              void* d_out, int out_size) {
    const float* pred = (const float*)d_in[0];
    const float* tru  = (const float*)d_in[1];
    float* out = (float*)d_out;

    dim3 grid(BLOCKS_X, BS);
    adaploss_fused<<<grid, THREADS>>>(pred, tru, out);
}